// round 13
// baseline (speedup 1.0000x reference)
#include <cuda_runtime.h>
#include <cuda_fp16.h>
#include <math.h>
#include <stdint.h>

// ---------------------------------------------------------------------------
// GPT block: B=4, S=2048, D_MODEL=1024, H=16, DK=64, DFF=4096, fp32, causal.
// Round-13: R12 + occupancy push: GEMM 2 stages -> 3 CTAs/SM (42% occ),
// attention occ 3. Everything else unchanged.
// ---------------------------------------------------------------------------

#define BATCH  4
#define SEQ    2048
#define DMODEL 1024
#define NHEAD  16
#define DHEAD  64
#define DFF    4096
#define MROWS  (BATCH * SEQ)   // 8192
#define MBTOT  (MROWS / 128)   // 64

// ---------------- fp32 scratch ----------------
__device__ float g_res1[MROWS * DMODEL];
__device__ float g_h[MROWS * DMODEL];
__device__ float g_res2[MROWS * DMODEL];
__device__ float g_bqkv[3 * DMODEL];

// ---------------- fp16 scratch ----------------
__device__ __align__(1024) __half g_x2hi[MROWS * DMODEL];
__device__ __align__(1024) __half g_ctx2hi[MROWS * DMODEL];
__device__ __align__(1024) __half g_h2hi[MROWS * DMODEL];
__device__ __align__(1024) __half g_ff2hi[(size_t)MROWS * DFF];
__device__ __align__(1024) __half g_Qh[MROWS * DMODEL];
__device__ __align__(1024) __half g_Kh[MROWS * DMODEL];
__device__ __align__(1024) __half g_Vh[MROWS * DMODEL];
__device__ __align__(1024) __half g_wqkvhi[3 * DMODEL * DMODEL];
__device__ __align__(1024) __half g_wohi[DMODEL * DMODEL];
__device__ __align__(1024) __half g_w1hi[DFF * DMODEL];
__device__ __align__(1024) __half g_w2hi[DMODEL * DFF];

// ---------------------------------------------------------------------------
// PTX helpers (base-target only)
// ---------------------------------------------------------------------------
__device__ __forceinline__ uint32_t smem_u32(const void* p) {
    uint32_t a;
    asm("{ .reg .u64 t; cvta.to.shared.u64 t, %1; cvt.u32.u64 %0, t; }" : "=r"(a) : "l"(p));
    return a;
}

#define MBARRIER_INIT(addr, cnt) \
    asm volatile("mbarrier.init.shared.b64 [%0], %1;" :: "r"((uint32_t)(addr)), "r"((uint32_t)(cnt)) : "memory")

#define MBARRIER_ARRIVE(addr) \
    asm volatile("mbarrier.arrive.shared.b64 _, [%0];" :: "r"((uint32_t)(addr)) : "memory")

#define MBARRIER_EXPECT_TX(addr, bytes) \
    asm volatile("mbarrier.arrive.expect_tx.shared.b64 _, [%0], %1;" :: "r"((uint32_t)(addr)), "r"((uint32_t)(bytes)) : "memory")

#define MBARRIER_WAIT_PARITY(mbar_smem_addr, phase_parity) do { \
    uint32_t _mbar = (uint32_t)(mbar_smem_addr); \
    uint32_t _parity = (uint32_t)(phase_parity); \
    uint32_t _done; \
    asm volatile( \
        "{\n\t.reg .pred p;\n\t" \
        "mbarrier.try_wait.parity.acquire.cta.shared::cta.b64 p, [%1], %2;\n\t" \
        "selp.b32 %0, 1, 0, p;\n\t}" \
        : "=r"(_done) : "r"(_mbar), "r"(_parity) : "memory"); \
    if (!_done) { \
        asm volatile( \
            "{\n\t.reg .pred P1;\n\t" \
            "WAIT_LOOP_%=:\n\t" \
            "mbarrier.try_wait.parity.acquire.cta.shared::cta.b64 P1, [%0], %1, 0x989680;\n\t" \
            "@P1 bra.uni WAIT_DONE_%=;\n\t" \
            "bra.uni WAIT_LOOP_%=;\n\t" \
            "WAIT_DONE_%=:\n\t}" \
            :: "r"(_mbar), "r"(_parity) : "memory"); \
    } \
} while(0)

__device__ __forceinline__ void bulk_g2s(uint32_t dst, const void* src, uint32_t bytes, uint32_t mbar) {
    asm volatile(
        "cp.async.bulk.shared::cluster.global.mbarrier::complete_tx::bytes [%0], [%1], %2, [%3];"
        :: "r"(dst), "l"(src), "r"(bytes), "r"(mbar) : "memory");
}

__device__ __forceinline__ void ldsm_x4(uint32_t* r, uint32_t addr) {
    asm volatile("ldmatrix.sync.aligned.m8n8.x4.shared.b16 {%0,%1,%2,%3}, [%4];"
        : "=r"(r[0]), "=r"(r[1]), "=r"(r[2]), "=r"(r[3]) : "r"(addr));
}

__device__ __forceinline__ void ldsm_x4_t(uint32_t* r, uint32_t addr) {
    asm volatile("ldmatrix.sync.aligned.m8n8.x4.trans.shared.b16 {%0,%1,%2,%3}, [%4];"
        : "=r"(r[0]), "=r"(r[1]), "=r"(r[2]), "=r"(r[3]) : "r"(addr));
}

__device__ __forceinline__ void mma_f16(float* d, const uint32_t* a, uint32_t b0, uint32_t b1) {
    asm volatile(
        "mma.sync.aligned.m16n8k16.row.col.f32.f16.f16.f32 "
        "{%0,%1,%2,%3}, {%4,%5,%6,%7}, {%8,%9}, {%0,%1,%2,%3};"
        : "+f"(d[0]), "+f"(d[1]), "+f"(d[2]), "+f"(d[3])
        : "r"(a[0]), "r"(a[1]), "r"(a[2]), "r"(a[3]), "r"(b0), "r"(b1));
}

__device__ __forceinline__ uint32_t pack_f16(float x, float y) {
    __half2 p = __floats2half2_rn(x, y);
    return *reinterpret_cast<uint32_t*>(&p);
}

// ---------------------------------------------------------------------------
// Vectorized conversion: 16 consecutive elems per thread (4096 per block).
// ---------------------------------------------------------------------------
__device__ __forceinline__ void conv4096_hi(
    const float* __restrict__ in, __half* __restrict__ hi,
    int K, int RBtot, int rb_off, int blk)
{
    const int e = blk * 4096 + threadIdx.x * 16;
    const int r = e / K;
    const int k = e - r * K;

    const float4* src = (const float4*)(in + (size_t)r * K + k);
    float4 v0 = src[0], v1 = src[1], v2 = src[2], v3 = src[3];

    uint4 h0, h1;
    h0.x = pack_f16(v0.x, v0.y); h0.y = pack_f16(v0.z, v0.w);
    h0.z = pack_f16(v1.x, v1.y); h0.w = pack_f16(v1.z, v1.w);
    h1.x = pack_f16(v2.x, v2.y); h1.y = pack_f16(v2.z, v2.w);
    h1.z = pack_f16(v3.x, v3.y); h1.w = pack_f16(v3.z, v3.w);

    const int kc = k >> 6;
    const int rb = (r >> 7) + rb_off;
    const int rr = r & 127;
    const int c  = k & 63;
    size_t blkbytes = ((size_t)kc * RBtot + rb) * 16384;
    uint32_t off0 = (uint32_t)(rr * 128 + c * 2);
    uint32_t off1 = off0 + 16;
    off0 ^= (off0 >> 3) & 0x70;
    off1 ^= (off1 >> 3) & 0x70;
    *reinterpret_cast<uint4*>((char*)hi + blkbytes + off0) = h0;
    *reinterpret_cast<uint4*>((char*)hi + blkbytes + off1) = h1;
}

__global__ void __launch_bounds__(256) convert_all_kernel(
    const float* __restrict__ x,
    const float* __restrict__ wq, const float* __restrict__ wk,
    const float* __restrict__ wv, const float* __restrict__ wo,
    const float* __restrict__ w1, const float* __restrict__ w2,
    const float* __restrict__ bq, const float* __restrict__ bk,
    const float* __restrict__ bv)
{
    const int bi = blockIdx.x;
    if (bi < 256) {
        conv4096_hi(wq, g_wqkvhi, DMODEL, 24, 0, bi);
    } else if (bi < 512) {
        conv4096_hi(wk, g_wqkvhi, DMODEL, 24, 8, bi - 256);
    } else if (bi < 768) {
        conv4096_hi(wv, g_wqkvhi, DMODEL, 24, 16, bi - 512);
    } else if (bi < 1024) {
        conv4096_hi(wo, g_wohi, DMODEL, 8, 0, bi - 768);
    } else if (bi < 2048) {
        conv4096_hi(w1, g_w1hi, DMODEL, 32, 0, bi - 1024);
    } else if (bi < 3072) {
        conv4096_hi(w2, g_w2hi, DFF, 8, 0, bi - 2048);
    } else if (bi < 5120) {
        conv4096_hi(x, g_x2hi, DMODEL, MBTOT, 0, bi - 3072);
    } else {
        const int which = bi - 5120;
        const float* src = (which == 0) ? bq : (which == 1) ? bk : bv;
        float4 v = *(const float4*)(src + threadIdx.x * 4);
        *(float4*)(g_bqkv + which * DMODEL + threadIdx.x * 4) = v;
    }
}

// ---------------------------------------------------------------------------
// HMMA GEMM, warp-specialized: 288 threads = 8 compute warps + 1 producer.
// BM=BN=128, chunk K=64, warp tile 64x32. Stage = 32KB, 2 stages, occ 3.
// ---------------------------------------------------------------------------
#define GEMM_STAGES 2
#define GEMM_STAGE_BYTES 32768
#define GEMM_SMEM_BYTES (1024 + GEMM_STAGES * GEMM_STAGE_BYTES)
#define GEMM_THREADS 288

template <int MODE>
__global__ void __launch_bounds__(GEMM_THREADS, 3) tc_gemm(
    const __half* __restrict__ Ahi, const __half* __restrict__ Whi,
    int KC, int MBtot, int NBtot,
    const float* __restrict__ bias, const float* __restrict__ add,
    float* __restrict__ C, int Ncols)
{
    extern __shared__ __align__(1024) char smem[];
    const uint32_t sb = smem_u32(smem);
    const uint32_t FULLB  = sb;
    const uint32_t EMPTYB = sb + 8 * GEMM_STAGES;
    const uint32_t DATA   = sb + 1024;

    const int tid = threadIdx.x;
    const int wid = tid >> 5;
    const int lane = tid & 31;
    const int mb = blockIdx.y;
    const int nb = blockIdx.x;
    const int m0 = mb * 128;
    const int n0 = nb * 128;

    if (tid == 0) {
        for (int s = 0; s < GEMM_STAGES; s++) {
            MBARRIER_INIT(FULLB + 8 * s, 1);
            MBARRIER_INIT(EMPTYB + 8 * s, 8);
        }
    }
    __syncthreads();

    if (wid == 8) {
        if (lane == 0) {
            for (int j = 0; j < KC; j++) {
                const int s = j % GEMM_STAGES;
                const uint32_t par = (uint32_t)(((j / GEMM_STAGES) + 1) & 1);
                MBARRIER_WAIT_PARITY(EMPTYB + 8 * s, par);
                const char* ah = (const char*)Ahi + ((size_t)j * MBtot + mb) * 16384;
                const char* wg = (const char*)Whi + ((size_t)j * NBtot + nb) * 16384;
                const uint32_t full = FULLB + 8 * s;
                MBARRIER_EXPECT_TX(full, GEMM_STAGE_BYTES);
                bulk_g2s(DATA + s * GEMM_STAGE_BYTES,         ah, 16384, full);
                bulk_g2s(DATA + s * GEMM_STAGE_BYTES + 16384, wg, 16384, full);
            }
        }
        return;
    }

    const int wm = (wid >> 2) * 64;
    const int wn = (wid & 3) * 32;

    float d[4][4][4];
#pragma unroll
    for (int mi = 0; mi < 4; mi++)
#pragma unroll
        for (int nj = 0; nj < 4; nj++)
#pragma unroll
            for (int r = 0; r < 4; r++) d[mi][nj][r] = 0.0f;

    const int rsel = lane & 15;
    const int ksel = (lane >> 4) << 3;

    int st = 0, phw = 0;
    for (int i = 0; i < KC; i++) {
        MBARRIER_WAIT_PARITY(FULLB + 8 * st, phw);
        const uint32_t Ab = DATA + st * GEMM_STAGE_BYTES;
        const uint32_t Bb = Ab + 16384;

#pragma unroll
        for (int ks = 0; ks < 4; ks++) {
            const uint32_t kc2 = (uint32_t)((ks * 16 + ksel) * 2);
            uint32_t bfr[4][2];
#pragma unroll
            for (int g = 0; g < 2; g++) {
                const int row = wn + g * 16 + rsel;
                uint32_t r4[4];
                ldsm_x4(r4, Bb + row * 128 + (kc2 ^ ((row & 7) << 4)));
                bfr[g * 2 + 0][0] = r4[0]; bfr[g * 2 + 0][1] = r4[2];
                bfr[g * 2 + 1][0] = r4[1]; bfr[g * 2 + 1][1] = r4[3];
            }
#pragma unroll
            for (int mi = 0; mi < 4; mi++) {
                const int row = wm + mi * 16 + rsel;
                uint32_t a[4];
                ldsm_x4(a, Ab + row * 128 + (kc2 ^ ((row & 7) << 4)));
#pragma unroll
                for (int nj = 0; nj < 4; nj++)
                    mma_f16(d[mi][nj], a, bfr[nj][0], bfr[nj][1]);
            }
        }

        if (lane == 0) MBARRIER_ARRIVE(EMPTYB + 8 * st);
        if (++st == GEMM_STAGES) { st = 0; phw ^= 1; }
    }

    // ------------------- epilogue -------------------
    const int gr = lane >> 2;
    const int gc = (lane & 3) << 1;
#pragma unroll
    for (int mi = 0; mi < 4; mi++) {
#pragma unroll
        for (int nj = 0; nj < 4; nj++) {
            const int col = n0 + wn + nj * 8 + gc;
            const float bx = bias[col], by = bias[col + 1];
#pragma unroll
            for (int half = 0; half < 2; half++) {
                const int m = m0 + wm + mi * 16 + gr + half * 8;
                float ox = d[mi][nj][half * 2 + 0] + bx;
                float oy = d[mi][nj][half * 2 + 1] + by;
                if (MODE == 0) {
                    const int which = col >> 10;
                    const int np = col & 1023;
                    const int hh = np >> 6;
                    const int dk = np & 63;
                    const int b = m >> 11;
                    const int s2 = m & (SEQ - 1);
                    size_t base = (((size_t)(b * NHEAD + hh)) * SEQ + (s2 & ~63)) * DHEAD;
                    uint32_t off = (uint32_t)((s2 & 63) * 128 + dk * 2);
                    off ^= (off >> 3) & 0x70;
                    if (which == 0) { ox *= 0.125f; oy *= 0.125f; }
                    __half* dh = (which == 0) ? g_Qh : (which == 1) ? g_Kh : g_Vh;
                    *(uint32_t*)((char*)(dh + base) + off) = pack_f16(ox, oy);
                } else if (MODE == 1) {
                    float2 a2 = *(const float2*)(add + (size_t)m * Ncols + col);
                    float2 o; o.x = ox + a2.x; o.y = oy + a2.y;
                    *(float2*)(C + (size_t)m * Ncols + col) = o;
                } else {
                    float gx = 0.5f * ox * (1.0f + erff(ox * 0.70710678118654752f));
                    float gy = 0.5f * oy * (1.0f + erff(oy * 0.70710678118654752f));
                    const int kc = col >> 6;
                    const int c = col & 63;
                    const int rb = m >> 7;
                    const int rr = m & 127;
                    size_t blkbytes = ((size_t)(kc * MBTOT + rb)) * 16384;
                    uint32_t off = (uint32_t)(rr * 128 + c * 2);
                    off ^= (off >> 3) & 0x70;
                    *(uint32_t*)((char*)g_ff2hi + blkbytes + off) = pack_f16(gx, gy);
                }
            }
        }
    }
}

// ---------------------------------------------------------------------------
// HMMA flash attention, fp16 single-term (128 thr, 64 q rows), occ 3.
// ---------------------------------------------------------------------------
#define ATT_STAGES 2
#define ATT_SMEM (1024 + 8192 + ATT_STAGES * 16384)

__global__ void __launch_bounds__(128, 3) attn_mma_kernel(
    const __half* __restrict__ Qh,
    const __half* __restrict__ Kh, const __half* __restrict__ Vh)
{
    extern __shared__ __align__(1024) char smem[];
    const uint32_t sb = smem_u32(smem);
    const uint32_t QBAR = sb;
    const uint32_t FULLB = sb + 8;
    const uint32_t SQ = sb + 1024;
    const uint32_t SKV = SQ + 8192;

    const int tid = threadIdx.x;
    const int wid = tid >> 5;
    const int lane = tid & 31;
    const int qt = blockIdx.x;
    const int hh = blockIdx.y;
    const int bb = blockIdx.z;
    const int q0 = qt * 64;
    const int T = qt + 1;

    const size_t headoff = (size_t)(bb * NHEAD + hh) * SEQ * DHEAD;

    if (tid == 0) {
        MBARRIER_INIT(QBAR, 1);
        MBARRIER_INIT(FULLB, 1);
        MBARRIER_INIT(FULLB + 8, 1);
    }
    __syncthreads();

    if (tid == 0) {
        MBARRIER_EXPECT_TX(QBAR, 8192);
        bulk_g2s(SQ, Qh + headoff + (size_t)qt * 4096, 8192, QBAR);
        const int pre = T < ATT_STAGES ? T : ATT_STAGES;
        for (int s = 0; s < pre; s++) {
            const uint32_t full = FULLB + 8 * s;
            MBARRIER_EXPECT_TX(full, 16384);
            const size_t kv = headoff + (size_t)s * 4096;
            bulk_g2s(SKV + s * 16384,        Kh + kv, 8192, full);
            bulk_g2s(SKV + s * 16384 + 8192, Vh + kv, 8192, full);
        }
    }

    float o[8][4];
#pragma unroll
    for (int nt = 0; nt < 8; nt++)
#pragma unroll
        for (int r = 0; r < 4; r++) o[nt][r] = 0.0f;
    float mi[2] = {-1e30f, -1e30f};
    float li[2] = {0.0f, 0.0f};

    const int rsel = lane & 15;
    const int ksel = (lane >> 4) << 3;
    const int gr = lane >> 2;
    const int gc = lane & 3;
    const int qw = wid * 16;

    MBARRIER_WAIT_PARITY(QBAR, 0);

    uint32_t aq[4][4];
    {
        const int qrow = qw + rsel;
        const uint32_t qsw = (uint32_t)((qrow & 7) << 4);
#pragma unroll
        for (int kc = 0; kc < 4; kc++) {
            const uint32_t kb = (uint32_t)((kc * 16 + ksel) * 2);
            ldsm_x4(aq[kc], SQ + qrow * 128 + (kb ^ qsw));
        }
    }

    for (int i = 0; i < T; i++) {
        const int st = i & 1;
        MBARRIER_WAIT_PARITY(FULLB + 8 * st, (i >> 1) & 1);
        const uint32_t Kb = SKV + st * 16384;
        const uint32_t Vb = Kb + 8192;

        float c[8][4];
#pragma unroll
        for (int nt = 0; nt < 8; nt++)
#pragma unroll
            for (int r = 0; r < 4; r++) c[nt][r] = 0.0f;

#pragma unroll
        for (int kc = 0; kc < 4; kc++) {
            const uint32_t kb = (uint32_t)((kc * 16 + ksel) * 2);
#pragma unroll
            for (int ntp = 0; ntp < 4; ntp++) {
                const int krow = ntp * 16 + rsel;
                const uint32_t koff = kb ^ ((krow & 7) << 4);
                uint32_t kh4[4];
                ldsm_x4(kh4, Kb + krow * 128 + koff);
                mma_f16(c[ntp * 2 + 0], aq[kc], kh4[0], kh4[2]);
                mma_f16(c[ntp * 2 + 1], aq[kc], kh4[1], kh4[3]);
            }
        }

        const int kv0 = i * 64;
        const int row0 = q0 + qw + gr;
        if (kv0 + 63 > q0 + qw) {
#pragma unroll
            for (int nt = 0; nt < 8; nt++) {
                const int col = kv0 + nt * 8 + gc * 2;
                if (col     > row0)     c[nt][0] = -1e30f;
                if (col + 1 > row0)     c[nt][1] = -1e30f;
                if (col     > row0 + 8) c[nt][2] = -1e30f;
                if (col + 1 > row0 + 8) c[nt][3] = -1e30f;
            }
        }

#pragma unroll
        for (int h2 = 0; h2 < 2; h2++) {
            float rm = -1e30f;
#pragma unroll
            for (int nt = 0; nt < 8; nt++)
                rm = fmaxf(rm, fmaxf(c[nt][h2 * 2], c[nt][h2 * 2 + 1]));
            rm = fmaxf(rm, __shfl_xor_sync(0xffffffffu, rm, 1));
            rm = fmaxf(rm, __shfl_xor_sync(0xffffffffu, rm, 2));
            const float mn = fmaxf(mi[h2], rm);
            const float corr = __expf(mi[h2] - mn);
            mi[h2] = mn;
            float rs = 0.0f;
#pragma unroll
            for (int nt = 0; nt < 8; nt++) {
                float p0 = __expf(c[nt][h2 * 2] - mn);
                float p1 = __expf(c[nt][h2 * 2 + 1] - mn);
                c[nt][h2 * 2] = p0; c[nt][h2 * 2 + 1] = p1;
                rs += p0 + p1;
            }
            rs += __shfl_xor_sync(0xffffffffu, rs, 1);
            rs += __shfl_xor_sync(0xffffffffu, rs, 2);
            li[h2] = li[h2] * corr + rs;
#pragma unroll
            for (int nt = 0; nt < 8; nt++) {
                o[nt][h2 * 2] *= corr; o[nt][h2 * 2 + 1] *= corr;
            }
        }

#pragma unroll
        for (int kc = 0; kc < 4; kc++) {
            uint32_t ph[4];
            ph[0] = pack_f16(c[2 * kc][0], c[2 * kc][1]);
            ph[1] = pack_f16(c[2 * kc][2], c[2 * kc][3]);
            ph[2] = pack_f16(c[2 * kc + 1][0], c[2 * kc + 1][1]);
            ph[3] = pack_f16(c[2 * kc + 1][2], c[2 * kc + 1][3]);

            const int krow = kc * 16 + rsel;
            const uint32_t swz = (uint32_t)((krow & 7) << 4);
#pragma unroll
            for (int ntd = 0; ntd < 4; ntd++) {
                const uint32_t cb = (uint32_t)((ntd * 16 + ksel) * 2);
                uint32_t vh4[4];
                ldsm_x4_t(vh4, Vb + krow * 128 + (cb ^ swz));
                mma_f16(o[ntd * 2 + 0], ph, vh4[0], vh4[1]);
                mma_f16(o[ntd * 2 + 1], ph, vh4[2], vh4[3]);
            }
        }

        __syncthreads();
        if (tid == 0 && i + ATT_STAGES < T) {
            const int j = i + ATT_STAGES;
            const uint32_t full = FULLB + 8 * st;
            MBARRIER_EXPECT_TX(full, 16384);
            const size_t kv = headoff + (size_t)j * 4096;
            bulk_g2s(SKV + st * 16384,        Kh + kv, 8192, full);
            bulk_g2s(SKV + st * 16384 + 8192, Vh + kv, 8192, full);
        }
    }

    const float inv0 = 1.0f / li[0];
    const float inv1 = 1.0f / li[1];
    const int mrow0 = bb * SEQ + q0 + qw + gr;
#pragma unroll
    for (int nt = 0; nt < 8; nt++) {
        const int dcol = nt * 8 + gc * 2;
#pragma unroll
        for (int h2 = 0; h2 < 2; h2++) {
            const int m = mrow0 + h2 * 8;
            const float vx = o[nt][h2 * 2] * (h2 ? inv1 : inv0);
            const float vy = o[nt][h2 * 2 + 1] * (h2 ? inv1 : inv0);
            const int rb = m >> 7;
            const int rr = m & 127;
            size_t blkbytes = ((size_t)(hh * MBTOT + rb)) * 16384;
            uint32_t off = (uint32_t)(rr * 128 + dcol * 2);
            off ^= (off >> 3) & 0x70;
            *(uint32_t*)((char*)g_ctx2hi + blkbytes + off) = pack_f16(vx, vy);
        }
    }
}

// ---------------------------------------------------------------------------
// LayerNorm; optionally also writes fp16 chunks.
// ---------------------------------------------------------------------------
__global__ void __launch_bounds__(256) ln_kernel(
    const float* __restrict__ in, const float* __restrict__ sc,
    const float* __restrict__ bi, float* __restrict__ out,
    __half* __restrict__ hi)
{
    __shared__ float red0[8], red1[8];
    __shared__ float s_mu, s_inv;
    const int row = blockIdx.x;
    const int tid = threadIdx.x;

    float4 x = ((const float4*)(in + (size_t)row * DMODEL))[tid];
    float sum = x.x + x.y + x.z + x.w;
    float sq  = x.x * x.x + x.y * x.y + x.z * x.z + x.w * x.w;
#pragma unroll
    for (int o = 16; o; o >>= 1) {
        sum += __shfl_xor_sync(0xffffffffu, sum, o);
        sq  += __shfl_xor_sync(0xffffffffu, sq, o);
    }
    if ((tid & 31) == 0) { red0[tid >> 5] = sum; red1[tid >> 5] = sq; }
    __syncthreads();
    if (tid < 32) {
        float s = (tid < 8) ? red0[tid] : 0.0f;
        float q = (tid < 8) ? red1[tid] : 0.0f;
#pragma unroll
        for (int o = 4; o; o >>= 1) {
            s += __shfl_xor_sync(0xffffffffu, s, o);
            q += __shfl_xor_sync(0xffffffffu, q, o);
        }
        if (tid == 0) {
            float mu = s * (1.0f / DMODEL);
            float var = q * (1.0f / DMODEL) - mu * mu;
            s_mu = mu;
            s_inv = rsqrtf(var + 1e-5f);
        }
    }
    __syncthreads();
    const float mu = s_mu, inv = s_inv;
    float4 g = ((const float4*)sc)[tid];
    float4 b = ((const float4*)bi)[tid];
    float4 o;
    o.x = (x.x - mu) * inv * g.x + b.x;
    o.y = (x.y - mu) * inv * g.y + b.y;
    o.z = (x.z - mu) * inv * g.z + b.z;
    o.w = (x.w - mu) * inv * g.w + b.w;
    ((float4*)(out + (size_t)row * DMODEL))[tid] = o;

    if (hi) {
        const int col = tid * 4;
        const int kc = col >> 6;
        const int c = col & 63;
        const int rb = row >> 7;
        const int rr = row & 127;
        size_t blkbytes = ((size_t)(kc * MBTOT + rb)) * 16384;
        uint32_t off = (uint32_t)(rr * 128 + c * 2);
        off ^= (off >> 3) & 0x70;
        uint2 hu;
        hu.x = pack_f16(o.x, o.y);
        hu.y = pack_f16(o.z, o.w);
        *reinterpret_cast<uint2*>((char*)hi + blkbytes + off) = hu;
    }
}

// ---------------------------------------------------------------------------
extern "C" void kernel_launch(void* const* d_in, const int* in_sizes, int n_in,
                              void* d_out, int out_size)
{
    (void)in_sizes; (void)n_in; (void)out_size;
    const float* x    = (const float*)d_in[0];
    const float* wq   = (const float*)d_in[2];
    const float* bq   = (const float*)d_in[3];
    const float* wk   = (const float*)d_in[4];
    const float* bk   = (const float*)d_in[5];
    const float* wv   = (const float*)d_in[6];
    const float* bv   = (const float*)d_in[7];
    const float* wo   = (const float*)d_in[8];
    const float* bo   = (const float*)d_in[9];
    const float* w1   = (const float*)d_in[10];
    const float* b1   = (const float*)d_in[11];
    const float* w2   = (const float*)d_in[12];
    const float* b2   = (const float*)d_in[13];
    const float* ln1s = (const float*)d_in[14];
    const float* ln1b = (const float*)d_in[15];
    const float* ln2s = (const float*)d_in[16];
    const float* ln2b = (const float*)d_in[17];
    float* out = (float*)d_out;

    float *res1, *h, *res2, *bqkv;
    cudaGetSymbolAddress((void**)&res1, g_res1);
    cudaGetSymbolAddress((void**)&h,    g_h);
    cudaGetSymbolAddress((void**)&res2, g_res2);
    cudaGetSymbolAddress((void**)&bqkv, g_bqkv);

    __half *x2h, *c2h, *h2h, *f2h;
    __half *wqkvh, *woh, *w1h, *w2h;
    __half *qh, *kh, *vh;
    cudaGetSymbolAddress((void**)&x2h, g_x2hi);
    cudaGetSymbolAddress((void**)&c2h, g_ctx2hi);
    cudaGetSymbolAddress((void**)&h2h, g_h2hi);
    cudaGetSymbolAddress((void**)&f2h, g_ff2hi);
    cudaGetSymbolAddress((void**)&wqkvh, g_wqkvhi);
    cudaGetSymbolAddress((void**)&woh, g_wohi);
    cudaGetSymbolAddress((void**)&w1h, g_w1hi);
    cudaGetSymbolAddress((void**)&w2h, g_w2hi);
    cudaGetSymbolAddress((void**)&qh, g_Qh);
    cudaGetSymbolAddress((void**)&kh, g_Kh);
    cudaGetSymbolAddress((void**)&vh, g_Vh);

    cudaFuncSetAttribute(tc_gemm<0>, cudaFuncAttributeMaxDynamicSharedMemorySize, GEMM_SMEM_BYTES);
    cudaFuncSetAttribute(tc_gemm<1>, cudaFuncAttributeMaxDynamicSharedMemorySize, GEMM_SMEM_BYTES);
    cudaFuncSetAttribute(tc_gemm<2>, cudaFuncAttributeMaxDynamicSharedMemorySize, GEMM_SMEM_BYTES);
    cudaFuncSetAttribute(attn_mma_kernel, cudaFuncAttributeMaxDynamicSharedMemorySize, ATT_SMEM);

    const dim3 blk256(256);
    const dim3 blkg(GEMM_THREADS);

    // --- all conversions + bias concat in one launch (vectorized) ---
    convert_all_kernel<<<5123, blk256>>>(x, wq, wk, wv, wo, w1, w2, bq, bk, bv);

    // --- QKV fused GEMM (N=3072) -> fp16 per-head tiles ---
    tc_gemm<0><<<dim3(24, MBTOT), blkg, GEMM_SMEM_BYTES>>>(
        x2h, wqkvh, DMODEL / 64, MBTOT, 24, bqkv, nullptr, nullptr, 3072);

    // --- HMMA flash attention -> ctx fp16 chunks ---
    attn_mma_kernel<<<dim3(SEQ / 64, NHEAD, BATCH), 128, ATT_SMEM>>>(qh, kh, vh);

    // --- O projection + residual(x) -> res1; LN1 -> h (fp32 + fp16 chunks) ---
    tc_gemm<1><<<dim3(8, MBTOT), blkg, GEMM_SMEM_BYTES>>>(
        c2h, woh, DMODEL / 64, MBTOT, 8, bo, x, res1, DMODEL);
    ln_kernel<<<MROWS, blk256>>>(res1, ln1s, ln1b, h, h2h);

    // --- FFN1 + GELU -> ff fp16 chunks directly ---
    tc_gemm<2><<<dim3(32, MBTOT), blkg, GEMM_SMEM_BYTES>>>(
        h2h, w1h, DMODEL / 64, MBTOT, 32, b1, nullptr, nullptr, DFF);

    // --- FFN2 + residual(h) -> res2; LN2 -> out ---
    tc_gemm<1><<<dim3(8, MBTOT), blkg, GEMM_SMEM_BYTES>>>(
        f2h, w2h, DFF / 64, MBTOT, 8, b2, h, res2, DMODEL);
    ln_kernel<<<MROWS, blk256>>>(res2, ln2s, ln2b, out, nullptr);
}

// round 14
// speedup vs baseline: 2.4890x; 2.4890x over previous
#include <cuda_runtime.h>
#include <cuda_fp16.h>
#include <math.h>
#include <stdint.h>

// ---------------------------------------------------------------------------
// GPT block: B=4, S=2048, D_MODEL=1024, H=16, DK=64, DFF=4096, fp32, causal.
// Round-14: revert GEMM to R12 (3 stages, occ 2, warp-specialized producer,
// regs 96 — occ-3 cap spilled accumulators in R13). Attention kept at occ 3
// (fits: ~100 regs < 170 cap, 3x41KB smem).
// ---------------------------------------------------------------------------

#define BATCH  4
#define SEQ    2048
#define DMODEL 1024
#define NHEAD  16
#define DHEAD  64
#define DFF    4096
#define MROWS  (BATCH * SEQ)   // 8192
#define MBTOT  (MROWS / 128)   // 64

// ---------------- fp32 scratch ----------------
__device__ float g_res1[MROWS * DMODEL];
__device__ float g_h[MROWS * DMODEL];
__device__ float g_res2[MROWS * DMODEL];
__device__ float g_bqkv[3 * DMODEL];

// ---------------- fp16 scratch ----------------
__device__ __align__(1024) __half g_x2hi[MROWS * DMODEL];
__device__ __align__(1024) __half g_ctx2hi[MROWS * DMODEL];
__device__ __align__(1024) __half g_h2hi[MROWS * DMODEL];
__device__ __align__(1024) __half g_ff2hi[(size_t)MROWS * DFF];
__device__ __align__(1024) __half g_Qh[MROWS * DMODEL];
__device__ __align__(1024) __half g_Kh[MROWS * DMODEL];
__device__ __align__(1024) __half g_Vh[MROWS * DMODEL];
__device__ __align__(1024) __half g_wqkvhi[3 * DMODEL * DMODEL];
__device__ __align__(1024) __half g_wohi[DMODEL * DMODEL];
__device__ __align__(1024) __half g_w1hi[DFF * DMODEL];
__device__ __align__(1024) __half g_w2hi[DMODEL * DFF];

// ---------------------------------------------------------------------------
// PTX helpers (base-target only)
// ---------------------------------------------------------------------------
__device__ __forceinline__ uint32_t smem_u32(const void* p) {
    uint32_t a;
    asm("{ .reg .u64 t; cvta.to.shared.u64 t, %1; cvt.u32.u64 %0, t; }" : "=r"(a) : "l"(p));
    return a;
}

#define MBARRIER_INIT(addr, cnt) \
    asm volatile("mbarrier.init.shared.b64 [%0], %1;" :: "r"((uint32_t)(addr)), "r"((uint32_t)(cnt)) : "memory")

#define MBARRIER_ARRIVE(addr) \
    asm volatile("mbarrier.arrive.shared.b64 _, [%0];" :: "r"((uint32_t)(addr)) : "memory")

#define MBARRIER_EXPECT_TX(addr, bytes) \
    asm volatile("mbarrier.arrive.expect_tx.shared.b64 _, [%0], %1;" :: "r"((uint32_t)(addr)), "r"((uint32_t)(bytes)) : "memory")

#define MBARRIER_WAIT_PARITY(mbar_smem_addr, phase_parity) do { \
    uint32_t _mbar = (uint32_t)(mbar_smem_addr); \
    uint32_t _parity = (uint32_t)(phase_parity); \
    uint32_t _done; \
    asm volatile( \
        "{\n\t.reg .pred p;\n\t" \
        "mbarrier.try_wait.parity.acquire.cta.shared::cta.b64 p, [%1], %2;\n\t" \
        "selp.b32 %0, 1, 0, p;\n\t}" \
        : "=r"(_done) : "r"(_mbar), "r"(_parity) : "memory"); \
    if (!_done) { \
        asm volatile( \
            "{\n\t.reg .pred P1;\n\t" \
            "WAIT_LOOP_%=:\n\t" \
            "mbarrier.try_wait.parity.acquire.cta.shared::cta.b64 P1, [%0], %1, 0x989680;\n\t" \
            "@P1 bra.uni WAIT_DONE_%=;\n\t" \
            "bra.uni WAIT_LOOP_%=;\n\t" \
            "WAIT_DONE_%=:\n\t}" \
            :: "r"(_mbar), "r"(_parity) : "memory"); \
    } \
} while(0)

__device__ __forceinline__ void bulk_g2s(uint32_t dst, const void* src, uint32_t bytes, uint32_t mbar) {
    asm volatile(
        "cp.async.bulk.shared::cluster.global.mbarrier::complete_tx::bytes [%0], [%1], %2, [%3];"
        :: "r"(dst), "l"(src), "r"(bytes), "r"(mbar) : "memory");
}

__device__ __forceinline__ void ldsm_x4(uint32_t* r, uint32_t addr) {
    asm volatile("ldmatrix.sync.aligned.m8n8.x4.shared.b16 {%0,%1,%2,%3}, [%4];"
        : "=r"(r[0]), "=r"(r[1]), "=r"(r[2]), "=r"(r[3]) : "r"(addr));
}

__device__ __forceinline__ void ldsm_x4_t(uint32_t* r, uint32_t addr) {
    asm volatile("ldmatrix.sync.aligned.m8n8.x4.trans.shared.b16 {%0,%1,%2,%3}, [%4];"
        : "=r"(r[0]), "=r"(r[1]), "=r"(r[2]), "=r"(r[3]) : "r"(addr));
}

__device__ __forceinline__ void mma_f16(float* d, const uint32_t* a, uint32_t b0, uint32_t b1) {
    asm volatile(
        "mma.sync.aligned.m16n8k16.row.col.f32.f16.f16.f32 "
        "{%0,%1,%2,%3}, {%4,%5,%6,%7}, {%8,%9}, {%0,%1,%2,%3};"
        : "+f"(d[0]), "+f"(d[1]), "+f"(d[2]), "+f"(d[3])
        : "r"(a[0]), "r"(a[1]), "r"(a[2]), "r"(a[3]), "r"(b0), "r"(b1));
}

__device__ __forceinline__ uint32_t pack_f16(float x, float y) {
    __half2 p = __floats2half2_rn(x, y);
    return *reinterpret_cast<uint32_t*>(&p);
}

// ---------------------------------------------------------------------------
// Vectorized conversion: 16 consecutive elems per thread (4096 per block).
// ---------------------------------------------------------------------------
__device__ __forceinline__ void conv4096_hi(
    const float* __restrict__ in, __half* __restrict__ hi,
    int K, int RBtot, int rb_off, int blk)
{
    const int e = blk * 4096 + threadIdx.x * 16;
    const int r = e / K;
    const int k = e - r * K;

    const float4* src = (const float4*)(in + (size_t)r * K + k);
    float4 v0 = src[0], v1 = src[1], v2 = src[2], v3 = src[3];

    uint4 h0, h1;
    h0.x = pack_f16(v0.x, v0.y); h0.y = pack_f16(v0.z, v0.w);
    h0.z = pack_f16(v1.x, v1.y); h0.w = pack_f16(v1.z, v1.w);
    h1.x = pack_f16(v2.x, v2.y); h1.y = pack_f16(v2.z, v2.w);
    h1.z = pack_f16(v3.x, v3.y); h1.w = pack_f16(v3.z, v3.w);

    const int kc = k >> 6;
    const int rb = (r >> 7) + rb_off;
    const int rr = r & 127;
    const int c  = k & 63;
    size_t blkbytes = ((size_t)kc * RBtot + rb) * 16384;
    uint32_t off0 = (uint32_t)(rr * 128 + c * 2);
    uint32_t off1 = off0 + 16;
    off0 ^= (off0 >> 3) & 0x70;
    off1 ^= (off1 >> 3) & 0x70;
    *reinterpret_cast<uint4*>((char*)hi + blkbytes + off0) = h0;
    *reinterpret_cast<uint4*>((char*)hi + blkbytes + off1) = h1;
}

__global__ void __launch_bounds__(256) convert_all_kernel(
    const float* __restrict__ x,
    const float* __restrict__ wq, const float* __restrict__ wk,
    const float* __restrict__ wv, const float* __restrict__ wo,
    const float* __restrict__ w1, const float* __restrict__ w2,
    const float* __restrict__ bq, const float* __restrict__ bk,
    const float* __restrict__ bv)
{
    const int bi = blockIdx.x;
    if (bi < 256) {
        conv4096_hi(wq, g_wqkvhi, DMODEL, 24, 0, bi);
    } else if (bi < 512) {
        conv4096_hi(wk, g_wqkvhi, DMODEL, 24, 8, bi - 256);
    } else if (bi < 768) {
        conv4096_hi(wv, g_wqkvhi, DMODEL, 24, 16, bi - 512);
    } else if (bi < 1024) {
        conv4096_hi(wo, g_wohi, DMODEL, 8, 0, bi - 768);
    } else if (bi < 2048) {
        conv4096_hi(w1, g_w1hi, DMODEL, 32, 0, bi - 1024);
    } else if (bi < 3072) {
        conv4096_hi(w2, g_w2hi, DFF, 8, 0, bi - 2048);
    } else if (bi < 5120) {
        conv4096_hi(x, g_x2hi, DMODEL, MBTOT, 0, bi - 3072);
    } else {
        const int which = bi - 5120;
        const float* src = (which == 0) ? bq : (which == 1) ? bk : bv;
        float4 v = *(const float4*)(src + threadIdx.x * 4);
        *(float4*)(g_bqkv + which * DMODEL + threadIdx.x * 4) = v;
    }
}

// ---------------------------------------------------------------------------
// HMMA GEMM, warp-specialized: 288 threads = 8 compute warps + 1 producer.
// BM=BN=128, chunk K=64, warp tile 64x32. Stage = 32KB, 3 stages, occ 2.
// ---------------------------------------------------------------------------
#define GEMM_STAGES 3
#define GEMM_STAGE_BYTES 32768
#define GEMM_SMEM_BYTES (1024 + GEMM_STAGES * GEMM_STAGE_BYTES)
#define GEMM_THREADS 288

template <int MODE>
__global__ void __launch_bounds__(GEMM_THREADS, 2) tc_gemm(
    const __half* __restrict__ Ahi, const __half* __restrict__ Whi,
    int KC, int MBtot, int NBtot,
    const float* __restrict__ bias, const float* __restrict__ add,
    float* __restrict__ C, int Ncols)
{
    extern __shared__ __align__(1024) char smem[];
    const uint32_t sb = smem_u32(smem);
    const uint32_t FULLB  = sb;
    const uint32_t EMPTYB = sb + 8 * GEMM_STAGES;
    const uint32_t DATA   = sb + 1024;

    const int tid = threadIdx.x;
    const int wid = tid >> 5;
    const int lane = tid & 31;
    const int mb = blockIdx.y;
    const int nb = blockIdx.x;
    const int m0 = mb * 128;
    const int n0 = nb * 128;

    if (tid == 0) {
        for (int s = 0; s < GEMM_STAGES; s++) {
            MBARRIER_INIT(FULLB + 8 * s, 1);
            MBARRIER_INIT(EMPTYB + 8 * s, 8);
        }
    }
    __syncthreads();

    if (wid == 8) {
        if (lane == 0) {
            for (int j = 0; j < KC; j++) {
                const int s = j % GEMM_STAGES;
                const uint32_t par = (uint32_t)(((j / GEMM_STAGES) + 1) & 1);
                MBARRIER_WAIT_PARITY(EMPTYB + 8 * s, par);
                const char* ah = (const char*)Ahi + ((size_t)j * MBtot + mb) * 16384;
                const char* wg = (const char*)Whi + ((size_t)j * NBtot + nb) * 16384;
                const uint32_t full = FULLB + 8 * s;
                MBARRIER_EXPECT_TX(full, GEMM_STAGE_BYTES);
                bulk_g2s(DATA + s * GEMM_STAGE_BYTES,         ah, 16384, full);
                bulk_g2s(DATA + s * GEMM_STAGE_BYTES + 16384, wg, 16384, full);
            }
        }
        return;
    }

    const int wm = (wid >> 2) * 64;
    const int wn = (wid & 3) * 32;

    float d[4][4][4];
#pragma unroll
    for (int mi = 0; mi < 4; mi++)
#pragma unroll
        for (int nj = 0; nj < 4; nj++)
#pragma unroll
            for (int r = 0; r < 4; r++) d[mi][nj][r] = 0.0f;

    const int rsel = lane & 15;
    const int ksel = (lane >> 4) << 3;

    int st = 0, phw = 0;
    for (int i = 0; i < KC; i++) {
        MBARRIER_WAIT_PARITY(FULLB + 8 * st, phw);
        const uint32_t Ab = DATA + st * GEMM_STAGE_BYTES;
        const uint32_t Bb = Ab + 16384;

#pragma unroll
        for (int ks = 0; ks < 4; ks++) {
            const uint32_t kc2 = (uint32_t)((ks * 16 + ksel) * 2);
            uint32_t bfr[4][2];
#pragma unroll
            for (int g = 0; g < 2; g++) {
                const int row = wn + g * 16 + rsel;
                uint32_t r4[4];
                ldsm_x4(r4, Bb + row * 128 + (kc2 ^ ((row & 7) << 4)));
                bfr[g * 2 + 0][0] = r4[0]; bfr[g * 2 + 0][1] = r4[2];
                bfr[g * 2 + 1][0] = r4[1]; bfr[g * 2 + 1][1] = r4[3];
            }
#pragma unroll
            for (int mi = 0; mi < 4; mi++) {
                const int row = wm + mi * 16 + rsel;
                uint32_t a[4];
                ldsm_x4(a, Ab + row * 128 + (kc2 ^ ((row & 7) << 4)));
#pragma unroll
                for (int nj = 0; nj < 4; nj++)
                    mma_f16(d[mi][nj], a, bfr[nj][0], bfr[nj][1]);
            }
        }

        if (lane == 0) MBARRIER_ARRIVE(EMPTYB + 8 * st);
        if (++st == GEMM_STAGES) { st = 0; phw ^= 1; }
    }

    // ------------------- epilogue -------------------
    const int gr = lane >> 2;
    const int gc = (lane & 3) << 1;
#pragma unroll
    for (int mi = 0; mi < 4; mi++) {
#pragma unroll
        for (int nj = 0; nj < 4; nj++) {
            const int col = n0 + wn + nj * 8 + gc;
            const float bx = bias[col], by = bias[col + 1];
#pragma unroll
            for (int half = 0; half < 2; half++) {
                const int m = m0 + wm + mi * 16 + gr + half * 8;
                float ox = d[mi][nj][half * 2 + 0] + bx;
                float oy = d[mi][nj][half * 2 + 1] + by;
                if (MODE == 0) {
                    const int which = col >> 10;
                    const int np = col & 1023;
                    const int hh = np >> 6;
                    const int dk = np & 63;
                    const int b = m >> 11;
                    const int s2 = m & (SEQ - 1);
                    size_t base = (((size_t)(b * NHEAD + hh)) * SEQ + (s2 & ~63)) * DHEAD;
                    uint32_t off = (uint32_t)((s2 & 63) * 128 + dk * 2);
                    off ^= (off >> 3) & 0x70;
                    if (which == 0) { ox *= 0.125f; oy *= 0.125f; }
                    __half* dh = (which == 0) ? g_Qh : (which == 1) ? g_Kh : g_Vh;
                    *(uint32_t*)((char*)(dh + base) + off) = pack_f16(ox, oy);
                } else if (MODE == 1) {
                    float2 a2 = *(const float2*)(add + (size_t)m * Ncols + col);
                    float2 o; o.x = ox + a2.x; o.y = oy + a2.y;
                    *(float2*)(C + (size_t)m * Ncols + col) = o;
                } else {
                    float gx = 0.5f * ox * (1.0f + erff(ox * 0.70710678118654752f));
                    float gy = 0.5f * oy * (1.0f + erff(oy * 0.70710678118654752f));
                    const int kc = col >> 6;
                    const int c = col & 63;
                    const int rb = m >> 7;
                    const int rr = m & 127;
                    size_t blkbytes = ((size_t)(kc * MBTOT + rb)) * 16384;
                    uint32_t off = (uint32_t)(rr * 128 + c * 2);
                    off ^= (off >> 3) & 0x70;
                    *(uint32_t*)((char*)g_ff2hi + blkbytes + off) = pack_f16(gx, gy);
                }
            }
        }
    }
}

// ---------------------------------------------------------------------------
// HMMA flash attention, fp16 single-term (128 thr, 64 q rows), occ 3.
// ---------------------------------------------------------------------------
#define ATT_STAGES 2
#define ATT_SMEM (1024 + 8192 + ATT_STAGES * 16384)

__global__ void __launch_bounds__(128, 3) attn_mma_kernel(
    const __half* __restrict__ Qh,
    const __half* __restrict__ Kh, const __half* __restrict__ Vh)
{
    extern __shared__ __align__(1024) char smem[];
    const uint32_t sb = smem_u32(smem);
    const uint32_t QBAR = sb;
    const uint32_t FULLB = sb + 8;
    const uint32_t SQ = sb + 1024;
    const uint32_t SKV = SQ + 8192;

    const int tid = threadIdx.x;
    const int wid = tid >> 5;
    const int lane = tid & 31;
    const int qt = blockIdx.x;
    const int hh = blockIdx.y;
    const int bb = blockIdx.z;
    const int q0 = qt * 64;
    const int T = qt + 1;

    const size_t headoff = (size_t)(bb * NHEAD + hh) * SEQ * DHEAD;

    if (tid == 0) {
        MBARRIER_INIT(QBAR, 1);
        MBARRIER_INIT(FULLB, 1);
        MBARRIER_INIT(FULLB + 8, 1);
    }
    __syncthreads();

    if (tid == 0) {
        MBARRIER_EXPECT_TX(QBAR, 8192);
        bulk_g2s(SQ, Qh + headoff + (size_t)qt * 4096, 8192, QBAR);
        const int pre = T < ATT_STAGES ? T : ATT_STAGES;
        for (int s = 0; s < pre; s++) {
            const uint32_t full = FULLB + 8 * s;
            MBARRIER_EXPECT_TX(full, 16384);
            const size_t kv = headoff + (size_t)s * 4096;
            bulk_g2s(SKV + s * 16384,        Kh + kv, 8192, full);
            bulk_g2s(SKV + s * 16384 + 8192, Vh + kv, 8192, full);
        }
    }

    float o[8][4];
#pragma unroll
    for (int nt = 0; nt < 8; nt++)
#pragma unroll
        for (int r = 0; r < 4; r++) o[nt][r] = 0.0f;
    float mi[2] = {-1e30f, -1e30f};
    float li[2] = {0.0f, 0.0f};

    const int rsel = lane & 15;
    const int ksel = (lane >> 4) << 3;
    const int gr = lane >> 2;
    const int gc = lane & 3;
    const int qw = wid * 16;

    MBARRIER_WAIT_PARITY(QBAR, 0);

    uint32_t aq[4][4];
    {
        const int qrow = qw + rsel;
        const uint32_t qsw = (uint32_t)((qrow & 7) << 4);
#pragma unroll
        for (int kc = 0; kc < 4; kc++) {
            const uint32_t kb = (uint32_t)((kc * 16 + ksel) * 2);
            ldsm_x4(aq[kc], SQ + qrow * 128 + (kb ^ qsw));
        }
    }

    for (int i = 0; i < T; i++) {
        const int st = i & 1;
        MBARRIER_WAIT_PARITY(FULLB + 8 * st, (i >> 1) & 1);
        const uint32_t Kb = SKV + st * 16384;
        const uint32_t Vb = Kb + 8192;

        float c[8][4];
#pragma unroll
        for (int nt = 0; nt < 8; nt++)
#pragma unroll
            for (int r = 0; r < 4; r++) c[nt][r] = 0.0f;

#pragma unroll
        for (int kc = 0; kc < 4; kc++) {
            const uint32_t kb = (uint32_t)((kc * 16 + ksel) * 2);
#pragma unroll
            for (int ntp = 0; ntp < 4; ntp++) {
                const int krow = ntp * 16 + rsel;
                const uint32_t koff = kb ^ ((krow & 7) << 4);
                uint32_t kh4[4];
                ldsm_x4(kh4, Kb + krow * 128 + koff);
                mma_f16(c[ntp * 2 + 0], aq[kc], kh4[0], kh4[2]);
                mma_f16(c[ntp * 2 + 1], aq[kc], kh4[1], kh4[3]);
            }
        }

        const int kv0 = i * 64;
        const int row0 = q0 + qw + gr;
        if (kv0 + 63 > q0 + qw) {
#pragma unroll
            for (int nt = 0; nt < 8; nt++) {
                const int col = kv0 + nt * 8 + gc * 2;
                if (col     > row0)     c[nt][0] = -1e30f;
                if (col + 1 > row0)     c[nt][1] = -1e30f;
                if (col     > row0 + 8) c[nt][2] = -1e30f;
                if (col + 1 > row0 + 8) c[nt][3] = -1e30f;
            }
        }

#pragma unroll
        for (int h2 = 0; h2 < 2; h2++) {
            float rm = -1e30f;
#pragma unroll
            for (int nt = 0; nt < 8; nt++)
                rm = fmaxf(rm, fmaxf(c[nt][h2 * 2], c[nt][h2 * 2 + 1]));
            rm = fmaxf(rm, __shfl_xor_sync(0xffffffffu, rm, 1));
            rm = fmaxf(rm, __shfl_xor_sync(0xffffffffu, rm, 2));
            const float mn = fmaxf(mi[h2], rm);
            const float corr = __expf(mi[h2] - mn);
            mi[h2] = mn;
            float rs = 0.0f;
#pragma unroll
            for (int nt = 0; nt < 8; nt++) {
                float p0 = __expf(c[nt][h2 * 2] - mn);
                float p1 = __expf(c[nt][h2 * 2 + 1] - mn);
                c[nt][h2 * 2] = p0; c[nt][h2 * 2 + 1] = p1;
                rs += p0 + p1;
            }
            rs += __shfl_xor_sync(0xffffffffu, rs, 1);
            rs += __shfl_xor_sync(0xffffffffu, rs, 2);
            li[h2] = li[h2] * corr + rs;
#pragma unroll
            for (int nt = 0; nt < 8; nt++) {
                o[nt][h2 * 2] *= corr; o[nt][h2 * 2 + 1] *= corr;
            }
        }

#pragma unroll
        for (int kc = 0; kc < 4; kc++) {
            uint32_t ph[4];
            ph[0] = pack_f16(c[2 * kc][0], c[2 * kc][1]);
            ph[1] = pack_f16(c[2 * kc][2], c[2 * kc][3]);
            ph[2] = pack_f16(c[2 * kc + 1][0], c[2 * kc + 1][1]);
            ph[3] = pack_f16(c[2 * kc + 1][2], c[2 * kc + 1][3]);

            const int krow = kc * 16 + rsel;
            const uint32_t swz = (uint32_t)((krow & 7) << 4);
#pragma unroll
            for (int ntd = 0; ntd < 4; ntd++) {
                const uint32_t cb = (uint32_t)((ntd * 16 + ksel) * 2);
                uint32_t vh4[4];
                ldsm_x4_t(vh4, Vb + krow * 128 + (cb ^ swz));
                mma_f16(o[ntd * 2 + 0], ph, vh4[0], vh4[1]);
                mma_f16(o[ntd * 2 + 1], ph, vh4[2], vh4[3]);
            }
        }

        __syncthreads();
        if (tid == 0 && i + ATT_STAGES < T) {
            const int j = i + ATT_STAGES;
            const uint32_t full = FULLB + 8 * st;
            MBARRIER_EXPECT_TX(full, 16384);
            const size_t kv = headoff + (size_t)j * 4096;
            bulk_g2s(SKV + st * 16384,        Kh + kv, 8192, full);
            bulk_g2s(SKV + st * 16384 + 8192, Vh + kv, 8192, full);
        }
    }

    const float inv0 = 1.0f / li[0];
    const float inv1 = 1.0f / li[1];
    const int mrow0 = bb * SEQ + q0 + qw + gr;
#pragma unroll
    for (int nt = 0; nt < 8; nt++) {
        const int dcol = nt * 8 + gc * 2;
#pragma unroll
        for (int h2 = 0; h2 < 2; h2++) {
            const int m = mrow0 + h2 * 8;
            const float vx = o[nt][h2 * 2] * (h2 ? inv1 : inv0);
            const float vy = o[nt][h2 * 2 + 1] * (h2 ? inv1 : inv0);
            const int rb = m >> 7;
            const int rr = m & 127;
            size_t blkbytes = ((size_t)(hh * MBTOT + rb)) * 16384;
            uint32_t off = (uint32_t)(rr * 128 + dcol * 2);
            off ^= (off >> 3) & 0x70;
            *(uint32_t*)((char*)g_ctx2hi + blkbytes + off) = pack_f16(vx, vy);
        }
    }
}

// ---------------------------------------------------------------------------
// LayerNorm; optionally also writes fp16 chunks.
// ---------------------------------------------------------------------------
__global__ void __launch_bounds__(256) ln_kernel(
    const float* __restrict__ in, const float* __restrict__ sc,
    const float* __restrict__ bi, float* __restrict__ out,
    __half* __restrict__ hi)
{
    __shared__ float red0[8], red1[8];
    __shared__ float s_mu, s_inv;
    const int row = blockIdx.x;
    const int tid = threadIdx.x;

    float4 x = ((const float4*)(in + (size_t)row * DMODEL))[tid];
    float sum = x.x + x.y + x.z + x.w;
    float sq  = x.x * x.x + x.y * x.y + x.z * x.z + x.w * x.w;
#pragma unroll
    for (int o = 16; o; o >>= 1) {
        sum += __shfl_xor_sync(0xffffffffu, sum, o);
        sq  += __shfl_xor_sync(0xffffffffu, sq, o);
    }
    if ((tid & 31) == 0) { red0[tid >> 5] = sum; red1[tid >> 5] = sq; }
    __syncthreads();
    if (tid < 32) {
        float s = (tid < 8) ? red0[tid] : 0.0f;
        float q = (tid < 8) ? red1[tid] : 0.0f;
#pragma unroll
        for (int o = 4; o; o >>= 1) {
            s += __shfl_xor_sync(0xffffffffu, s, o);
            q += __shfl_xor_sync(0xffffffffu, q, o);
        }
        if (tid == 0) {
            float mu = s * (1.0f / DMODEL);
            float var = q * (1.0f / DMODEL) - mu * mu;
            s_mu = mu;
            s_inv = rsqrtf(var + 1e-5f);
        }
    }
    __syncthreads();
    const float mu = s_mu, inv = s_inv;
    float4 g = ((const float4*)sc)[tid];
    float4 b = ((const float4*)bi)[tid];
    float4 o;
    o.x = (x.x - mu) * inv * g.x + b.x;
    o.y = (x.y - mu) * inv * g.y + b.y;
    o.z = (x.z - mu) * inv * g.z + b.z;
    o.w = (x.w - mu) * inv * g.w + b.w;
    ((float4*)(out + (size_t)row * DMODEL))[tid] = o;

    if (hi) {
        const int col = tid * 4;
        const int kc = col >> 6;
        const int c = col & 63;
        const int rb = row >> 7;
        const int rr = row & 127;
        size_t blkbytes = ((size_t)(kc * MBTOT + rb)) * 16384;
        uint32_t off = (uint32_t)(rr * 128 + c * 2);
        off ^= (off >> 3) & 0x70;
        uint2 hu;
        hu.x = pack_f16(o.x, o.y);
        hu.y = pack_f16(o.z, o.w);
        *reinterpret_cast<uint2*>((char*)hi + blkbytes + off) = hu;
    }
}

// ---------------------------------------------------------------------------
extern "C" void kernel_launch(void* const* d_in, const int* in_sizes, int n_in,
                              void* d_out, int out_size)
{
    (void)in_sizes; (void)n_in; (void)out_size;
    const float* x    = (const float*)d_in[0];
    const float* wq   = (const float*)d_in[2];
    const float* bq   = (const float*)d_in[3];
    const float* wk   = (const float*)d_in[4];
    const float* bk   = (const float*)d_in[5];
    const float* wv   = (const float*)d_in[6];
    const float* bv   = (const float*)d_in[7];
    const float* wo   = (const float*)d_in[8];
    const float* bo   = (const float*)d_in[9];
    const float* w1   = (const float*)d_in[10];
    const float* b1   = (const float*)d_in[11];
    const float* w2   = (const float*)d_in[12];
    const float* b2   = (const float*)d_in[13];
    const float* ln1s = (const float*)d_in[14];
    const float* ln1b = (const float*)d_in[15];
    const float* ln2s = (const float*)d_in[16];
    const float* ln2b = (const float*)d_in[17];
    float* out = (float*)d_out;

    float *res1, *h, *res2, *bqkv;
    cudaGetSymbolAddress((void**)&res1, g_res1);
    cudaGetSymbolAddress((void**)&h,    g_h);
    cudaGetSymbolAddress((void**)&res2, g_res2);
    cudaGetSymbolAddress((void**)&bqkv, g_bqkv);

    __half *x2h, *c2h, *h2h, *f2h;
    __half *wqkvh, *woh, *w1h, *w2h;
    __half *qh, *kh, *vh;
    cudaGetSymbolAddress((void**)&x2h, g_x2hi);
    cudaGetSymbolAddress((void**)&c2h, g_ctx2hi);
    cudaGetSymbolAddress((void**)&h2h, g_h2hi);
    cudaGetSymbolAddress((void**)&f2h, g_ff2hi);
    cudaGetSymbolAddress((void**)&wqkvh, g_wqkvhi);
    cudaGetSymbolAddress((void**)&woh, g_wohi);
    cudaGetSymbolAddress((void**)&w1h, g_w1hi);
    cudaGetSymbolAddress((void**)&w2h, g_w2hi);
    cudaGetSymbolAddress((void**)&qh, g_Qh);
    cudaGetSymbolAddress((void**)&kh, g_Kh);
    cudaGetSymbolAddress((void**)&vh, g_Vh);

    cudaFuncSetAttribute(tc_gemm<0>, cudaFuncAttributeMaxDynamicSharedMemorySize, GEMM_SMEM_BYTES);
    cudaFuncSetAttribute(tc_gemm<1>, cudaFuncAttributeMaxDynamicSharedMemorySize, GEMM_SMEM_BYTES);
    cudaFuncSetAttribute(tc_gemm<2>, cudaFuncAttributeMaxDynamicSharedMemorySize, GEMM_SMEM_BYTES);
    cudaFuncSetAttribute(attn_mma_kernel, cudaFuncAttributeMaxDynamicSharedMemorySize, ATT_SMEM);

    const dim3 blk256(256);
    const dim3 blkg(GEMM_THREADS);

    // --- all conversions + bias concat in one launch (vectorized) ---
    convert_all_kernel<<<5123, blk256>>>(x, wq, wk, wv, wo, w1, w2, bq, bk, bv);

    // --- QKV fused GEMM (N=3072) -> fp16 per-head tiles ---
    tc_gemm<0><<<dim3(24, MBTOT), blkg, GEMM_SMEM_BYTES>>>(
        x2h, wqkvh, DMODEL / 64, MBTOT, 24, bqkv, nullptr, nullptr, 3072);

    // --- HMMA flash attention -> ctx fp16 chunks ---
    attn_mma_kernel<<<dim3(SEQ / 64, NHEAD, BATCH), 128, ATT_SMEM>>>(qh, kh, vh);

    // --- O projection + residual(x) -> res1; LN1 -> h (fp32 + fp16 chunks) ---
    tc_gemm<1><<<dim3(8, MBTOT), blkg, GEMM_SMEM_BYTES>>>(
        c2h, woh, DMODEL / 64, MBTOT, 8, bo, x, res1, DMODEL);
    ln_kernel<<<MROWS, blk256>>>(res1, ln1s, ln1b, h, h2h);

    // --- FFN1 + GELU -> ff fp16 chunks directly ---
    tc_gemm<2><<<dim3(32, MBTOT), blkg, GEMM_SMEM_BYTES>>>(
        h2h, w1h, DMODEL / 64, MBTOT, 32, b1, nullptr, nullptr, DFF);

    // --- FFN2 + residual(h) -> res2; LN2 -> out ---
    tc_gemm<1><<<dim3(8, MBTOT), blkg, GEMM_SMEM_BYTES>>>(
        f2h, w2h, DFF / 64, MBTOT, 8, b2, h, res2, DMODEL);
    ln_kernel<<<MROWS, blk256>>>(res2, ln2s, ln2b, out, nullptr);
}

// round 15
// speedup vs baseline: 2.4901x; 1.0005x over previous
#include <cuda_runtime.h>
#include <cuda_fp16.h>
#include <math.h>
#include <stdint.h>

// ---------------------------------------------------------------------------
// GPT block: B=4, S=2048, D_MODEL=1024, H=16, DK=64, DFF=4096, fp32, causal.
// Round-15: R14 best config + early empty-arrive in GEMM (signal stage free
// right after the last LDSM of the chunk, before trailing MMAs).
// ---------------------------------------------------------------------------

#define BATCH  4
#define SEQ    2048
#define DMODEL 1024
#define NHEAD  16
#define DHEAD  64
#define DFF    4096
#define MROWS  (BATCH * SEQ)   // 8192
#define MBTOT  (MROWS / 128)   // 64

// ---------------- fp32 scratch ----------------
__device__ float g_res1[MROWS * DMODEL];
__device__ float g_h[MROWS * DMODEL];
__device__ float g_res2[MROWS * DMODEL];
__device__ float g_bqkv[3 * DMODEL];

// ---------------- fp16 scratch ----------------
__device__ __align__(1024) __half g_x2hi[MROWS * DMODEL];
__device__ __align__(1024) __half g_ctx2hi[MROWS * DMODEL];
__device__ __align__(1024) __half g_h2hi[MROWS * DMODEL];
__device__ __align__(1024) __half g_ff2hi[(size_t)MROWS * DFF];
__device__ __align__(1024) __half g_Qh[MROWS * DMODEL];
__device__ __align__(1024) __half g_Kh[MROWS * DMODEL];
__device__ __align__(1024) __half g_Vh[MROWS * DMODEL];
__device__ __align__(1024) __half g_wqkvhi[3 * DMODEL * DMODEL];
__device__ __align__(1024) __half g_wohi[DMODEL * DMODEL];
__device__ __align__(1024) __half g_w1hi[DFF * DMODEL];
__device__ __align__(1024) __half g_w2hi[DMODEL * DFF];

// ---------------------------------------------------------------------------
// PTX helpers (base-target only)
// ---------------------------------------------------------------------------
__device__ __forceinline__ uint32_t smem_u32(const void* p) {
    uint32_t a;
    asm("{ .reg .u64 t; cvta.to.shared.u64 t, %1; cvt.u32.u64 %0, t; }" : "=r"(a) : "l"(p));
    return a;
}

#define MBARRIER_INIT(addr, cnt) \
    asm volatile("mbarrier.init.shared.b64 [%0], %1;" :: "r"((uint32_t)(addr)), "r"((uint32_t)(cnt)) : "memory")

#define MBARRIER_ARRIVE(addr) \
    asm volatile("mbarrier.arrive.shared.b64 _, [%0];" :: "r"((uint32_t)(addr)) : "memory")

#define MBARRIER_EXPECT_TX(addr, bytes) \
    asm volatile("mbarrier.arrive.expect_tx.shared.b64 _, [%0], %1;" :: "r"((uint32_t)(addr)), "r"((uint32_t)(bytes)) : "memory")

#define MBARRIER_WAIT_PARITY(mbar_smem_addr, phase_parity) do { \
    uint32_t _mbar = (uint32_t)(mbar_smem_addr); \
    uint32_t _parity = (uint32_t)(phase_parity); \
    uint32_t _done; \
    asm volatile( \
        "{\n\t.reg .pred p;\n\t" \
        "mbarrier.try_wait.parity.acquire.cta.shared::cta.b64 p, [%1], %2;\n\t" \
        "selp.b32 %0, 1, 0, p;\n\t}" \
        : "=r"(_done) : "r"(_mbar), "r"(_parity) : "memory"); \
    if (!_done) { \
        asm volatile( \
            "{\n\t.reg .pred P1;\n\t" \
            "WAIT_LOOP_%=:\n\t" \
            "mbarrier.try_wait.parity.acquire.cta.shared::cta.b64 P1, [%0], %1, 0x989680;\n\t" \
            "@P1 bra.uni WAIT_DONE_%=;\n\t" \
            "bra.uni WAIT_LOOP_%=;\n\t" \
            "WAIT_DONE_%=:\n\t}" \
            :: "r"(_mbar), "r"(_parity) : "memory"); \
    } \
} while(0)

__device__ __forceinline__ void bulk_g2s(uint32_t dst, const void* src, uint32_t bytes, uint32_t mbar) {
    asm volatile(
        "cp.async.bulk.shared::cluster.global.mbarrier::complete_tx::bytes [%0], [%1], %2, [%3];"
        :: "r"(dst), "l"(src), "r"(bytes), "r"(mbar) : "memory");
}

__device__ __forceinline__ void ldsm_x4(uint32_t* r, uint32_t addr) {
    asm volatile("ldmatrix.sync.aligned.m8n8.x4.shared.b16 {%0,%1,%2,%3}, [%4];"
        : "=r"(r[0]), "=r"(r[1]), "=r"(r[2]), "=r"(r[3]) : "r"(addr));
}

__device__ __forceinline__ void ldsm_x4_t(uint32_t* r, uint32_t addr) {
    asm volatile("ldmatrix.sync.aligned.m8n8.x4.trans.shared.b16 {%0,%1,%2,%3}, [%4];"
        : "=r"(r[0]), "=r"(r[1]), "=r"(r[2]), "=r"(r[3]) : "r"(addr));
}

__device__ __forceinline__ void mma_f16(float* d, const uint32_t* a, uint32_t b0, uint32_t b1) {
    asm volatile(
        "mma.sync.aligned.m16n8k16.row.col.f32.f16.f16.f32 "
        "{%0,%1,%2,%3}, {%4,%5,%6,%7}, {%8,%9}, {%0,%1,%2,%3};"
        : "+f"(d[0]), "+f"(d[1]), "+f"(d[2]), "+f"(d[3])
        : "r"(a[0]), "r"(a[1]), "r"(a[2]), "r"(a[3]), "r"(b0), "r"(b1));
}

__device__ __forceinline__ uint32_t pack_f16(float x, float y) {
    __half2 p = __floats2half2_rn(x, y);
    return *reinterpret_cast<uint32_t*>(&p);
}

// ---------------------------------------------------------------------------
// Vectorized conversion: 16 consecutive elems per thread (4096 per block).
// ---------------------------------------------------------------------------
__device__ __forceinline__ void conv4096_hi(
    const float* __restrict__ in, __half* __restrict__ hi,
    int K, int RBtot, int rb_off, int blk)
{
    const int e = blk * 4096 + threadIdx.x * 16;
    const int r = e / K;
    const int k = e - r * K;

    const float4* src = (const float4*)(in + (size_t)r * K + k);
    float4 v0 = src[0], v1 = src[1], v2 = src[2], v3 = src[3];

    uint4 h0, h1;
    h0.x = pack_f16(v0.x, v0.y); h0.y = pack_f16(v0.z, v0.w);
    h0.z = pack_f16(v1.x, v1.y); h0.w = pack_f16(v1.z, v1.w);
    h1.x = pack_f16(v2.x, v2.y); h1.y = pack_f16(v2.z, v2.w);
    h1.z = pack_f16(v3.x, v3.y); h1.w = pack_f16(v3.z, v3.w);

    const int kc = k >> 6;
    const int rb = (r >> 7) + rb_off;
    const int rr = r & 127;
    const int c  = k & 63;
    size_t blkbytes = ((size_t)kc * RBtot + rb) * 16384;
    uint32_t off0 = (uint32_t)(rr * 128 + c * 2);
    uint32_t off1 = off0 + 16;
    off0 ^= (off0 >> 3) & 0x70;
    off1 ^= (off1 >> 3) & 0x70;
    *reinterpret_cast<uint4*>((char*)hi + blkbytes + off0) = h0;
    *reinterpret_cast<uint4*>((char*)hi + blkbytes + off1) = h1;
}

__global__ void __launch_bounds__(256) convert_all_kernel(
    const float* __restrict__ x,
    const float* __restrict__ wq, const float* __restrict__ wk,
    const float* __restrict__ wv, const float* __restrict__ wo,
    const float* __restrict__ w1, const float* __restrict__ w2,
    const float* __restrict__ bq, const float* __restrict__ bk,
    const float* __restrict__ bv)
{
    const int bi = blockIdx.x;
    if (bi < 256) {
        conv4096_hi(wq, g_wqkvhi, DMODEL, 24, 0, bi);
    } else if (bi < 512) {
        conv4096_hi(wk, g_wqkvhi, DMODEL, 24, 8, bi - 256);
    } else if (bi < 768) {
        conv4096_hi(wv, g_wqkvhi, DMODEL, 24, 16, bi - 512);
    } else if (bi < 1024) {
        conv4096_hi(wo, g_wohi, DMODEL, 8, 0, bi - 768);
    } else if (bi < 2048) {
        conv4096_hi(w1, g_w1hi, DMODEL, 32, 0, bi - 1024);
    } else if (bi < 3072) {
        conv4096_hi(w2, g_w2hi, DFF, 8, 0, bi - 2048);
    } else if (bi < 5120) {
        conv4096_hi(x, g_x2hi, DMODEL, MBTOT, 0, bi - 3072);
    } else {
        const int which = bi - 5120;
        const float* src = (which == 0) ? bq : (which == 1) ? bk : bv;
        float4 v = *(const float4*)(src + threadIdx.x * 4);
        *(float4*)(g_bqkv + which * DMODEL + threadIdx.x * 4) = v;
    }
}

// ---------------------------------------------------------------------------
// HMMA GEMM, warp-specialized: 288 threads = 8 compute warps + 1 producer.
// BM=BN=128, chunk K=64, warp tile 64x32. Stage = 32KB, 3 stages, occ 2.
// Early empty-arrive: stage freed right after the chunk's final LDSM.
// ---------------------------------------------------------------------------
#define GEMM_STAGES 3
#define GEMM_STAGE_BYTES 32768
#define GEMM_SMEM_BYTES (1024 + GEMM_STAGES * GEMM_STAGE_BYTES)
#define GEMM_THREADS 288

template <int MODE>
__global__ void __launch_bounds__(GEMM_THREADS, 2) tc_gemm(
    const __half* __restrict__ Ahi, const __half* __restrict__ Whi,
    int KC, int MBtot, int NBtot,
    const float* __restrict__ bias, const float* __restrict__ add,
    float* __restrict__ C, int Ncols)
{
    extern __shared__ __align__(1024) char smem[];
    const uint32_t sb = smem_u32(smem);
    const uint32_t FULLB  = sb;
    const uint32_t EMPTYB = sb + 8 * GEMM_STAGES;
    const uint32_t DATA   = sb + 1024;

    const int tid = threadIdx.x;
    const int wid = tid >> 5;
    const int lane = tid & 31;
    const int mb = blockIdx.y;
    const int nb = blockIdx.x;
    const int m0 = mb * 128;
    const int n0 = nb * 128;

    if (tid == 0) {
        for (int s = 0; s < GEMM_STAGES; s++) {
            MBARRIER_INIT(FULLB + 8 * s, 1);
            MBARRIER_INIT(EMPTYB + 8 * s, 8);
        }
    }
    __syncthreads();

    if (wid == 8) {
        if (lane == 0) {
            for (int j = 0; j < KC; j++) {
                const int s = j % GEMM_STAGES;
                const uint32_t par = (uint32_t)(((j / GEMM_STAGES) + 1) & 1);
                MBARRIER_WAIT_PARITY(EMPTYB + 8 * s, par);
                const char* ah = (const char*)Ahi + ((size_t)j * MBtot + mb) * 16384;
                const char* wg = (const char*)Whi + ((size_t)j * NBtot + nb) * 16384;
                const uint32_t full = FULLB + 8 * s;
                MBARRIER_EXPECT_TX(full, GEMM_STAGE_BYTES);
                bulk_g2s(DATA + s * GEMM_STAGE_BYTES,         ah, 16384, full);
                bulk_g2s(DATA + s * GEMM_STAGE_BYTES + 16384, wg, 16384, full);
            }
        }
        return;
    }

    const int wm = (wid >> 2) * 64;
    const int wn = (wid & 3) * 32;

    float d[4][4][4];
#pragma unroll
    for (int mi = 0; mi < 4; mi++)
#pragma unroll
        for (int nj = 0; nj < 4; nj++)
#pragma unroll
            for (int r = 0; r < 4; r++) d[mi][nj][r] = 0.0f;

    const int rsel = lane & 15;
    const int ksel = (lane >> 4) << 3;

    int st = 0, phw = 0;
    for (int i = 0; i < KC; i++) {
        MBARRIER_WAIT_PARITY(FULLB + 8 * st, phw);
        const uint32_t Ab = DATA + st * GEMM_STAGE_BYTES;
        const uint32_t Bb = Ab + 16384;

#pragma unroll
        for (int ks = 0; ks < 4; ks++) {
            const uint32_t kc2 = (uint32_t)((ks * 16 + ksel) * 2);
            uint32_t bfr[4][2];
#pragma unroll
            for (int g = 0; g < 2; g++) {
                const int row = wn + g * 16 + rsel;
                uint32_t r4[4];
                ldsm_x4(r4, Bb + row * 128 + (kc2 ^ ((row & 7) << 4)));
                bfr[g * 2 + 0][0] = r4[0]; bfr[g * 2 + 0][1] = r4[2];
                bfr[g * 2 + 1][0] = r4[1]; bfr[g * 2 + 1][1] = r4[3];
            }
            uint32_t a[4][4];
#pragma unroll
            for (int mi = 0; mi < 4; mi++) {
                const int row = wm + mi * 16 + rsel;
                ldsm_x4(a[mi], Ab + row * 128 + (kc2 ^ ((row & 7) << 4)));
            }
            // all smem reads for this chunk done after last ks load batch:
            if (ks == 3 && lane == 0) MBARRIER_ARRIVE(EMPTYB + 8 * st);
#pragma unroll
            for (int mi = 0; mi < 4; mi++)
#pragma unroll
                for (int nj = 0; nj < 4; nj++)
                    mma_f16(d[mi][nj], a[mi], bfr[nj][0], bfr[nj][1]);
        }

        if (++st == GEMM_STAGES) { st = 0; phw ^= 1; }
    }

    // ------------------- epilogue -------------------
    const int gr = lane >> 2;
    const int gc = (lane & 3) << 1;
#pragma unroll
    for (int mi = 0; mi < 4; mi++) {
#pragma unroll
        for (int nj = 0; nj < 4; nj++) {
            const int col = n0 + wn + nj * 8 + gc;
            const float bx = bias[col], by = bias[col + 1];
#pragma unroll
            for (int half = 0; half < 2; half++) {
                const int m = m0 + wm + mi * 16 + gr + half * 8;
                float ox = d[mi][nj][half * 2 + 0] + bx;
                float oy = d[mi][nj][half * 2 + 1] + by;
                if (MODE == 0) {
                    const int which = col >> 10;
                    const int np = col & 1023;
                    const int hh = np >> 6;
                    const int dk = np & 63;
                    const int b = m >> 11;
                    const int s2 = m & (SEQ - 1);
                    size_t base = (((size_t)(b * NHEAD + hh)) * SEQ + (s2 & ~63)) * DHEAD;
                    uint32_t off = (uint32_t)((s2 & 63) * 128 + dk * 2);
                    off ^= (off >> 3) & 0x70;
                    if (which == 0) { ox *= 0.125f; oy *= 0.125f; }
                    __half* dh = (which == 0) ? g_Qh : (which == 1) ? g_Kh : g_Vh;
                    *(uint32_t*)((char*)(dh + base) + off) = pack_f16(ox, oy);
                } else if (MODE == 1) {
                    float2 a2 = *(const float2*)(add + (size_t)m * Ncols + col);
                    float2 o; o.x = ox + a2.x; o.y = oy + a2.y;
                    *(float2*)(C + (size_t)m * Ncols + col) = o;
                } else {
                    float gx = 0.5f * ox * (1.0f + erff(ox * 0.70710678118654752f));
                    float gy = 0.5f * oy * (1.0f + erff(oy * 0.70710678118654752f));
                    const int kc = col >> 6;
                    const int c = col & 63;
                    const int rb = m >> 7;
                    const int rr = m & 127;
                    size_t blkbytes = ((size_t)(kc * MBTOT + rb)) * 16384;
                    uint32_t off = (uint32_t)(rr * 128 + c * 2);
                    off ^= (off >> 3) & 0x70;
                    *(uint32_t*)((char*)g_ff2hi + blkbytes + off) = pack_f16(gx, gy);
                }
            }
        }
    }
}

// ---------------------------------------------------------------------------
// HMMA flash attention, fp16 single-term (128 thr, 64 q rows), occ 3.
// ---------------------------------------------------------------------------
#define ATT_STAGES 2
#define ATT_SMEM (1024 + 8192 + ATT_STAGES * 16384)

__global__ void __launch_bounds__(128, 3) attn_mma_kernel(
    const __half* __restrict__ Qh,
    const __half* __restrict__ Kh, const __half* __restrict__ Vh)
{
    extern __shared__ __align__(1024) char smem[];
    const uint32_t sb = smem_u32(smem);
    const uint32_t QBAR = sb;
    const uint32_t FULLB = sb + 8;
    const uint32_t SQ = sb + 1024;
    const uint32_t SKV = SQ + 8192;

    const int tid = threadIdx.x;
    const int wid = tid >> 5;
    const int lane = tid & 31;
    const int qt = blockIdx.x;
    const int hh = blockIdx.y;
    const int bb = blockIdx.z;
    const int q0 = qt * 64;
    const int T = qt + 1;

    const size_t headoff = (size_t)(bb * NHEAD + hh) * SEQ * DHEAD;

    if (tid == 0) {
        MBARRIER_INIT(QBAR, 1);
        MBARRIER_INIT(FULLB, 1);
        MBARRIER_INIT(FULLB + 8, 1);
    }
    __syncthreads();

    if (tid == 0) {
        MBARRIER_EXPECT_TX(QBAR, 8192);
        bulk_g2s(SQ, Qh + headoff + (size_t)qt * 4096, 8192, QBAR);
        const int pre = T < ATT_STAGES ? T : ATT_STAGES;
        for (int s = 0; s < pre; s++) {
            const uint32_t full = FULLB + 8 * s;
            MBARRIER_EXPECT_TX(full, 16384);
            const size_t kv = headoff + (size_t)s * 4096;
            bulk_g2s(SKV + s * 16384,        Kh + kv, 8192, full);
            bulk_g2s(SKV + s * 16384 + 8192, Vh + kv, 8192, full);
        }
    }

    float o[8][4];
#pragma unroll
    for (int nt = 0; nt < 8; nt++)
#pragma unroll
        for (int r = 0; r < 4; r++) o[nt][r] = 0.0f;
    float mi[2] = {-1e30f, -1e30f};
    float li[2] = {0.0f, 0.0f};

    const int rsel = lane & 15;
    const int ksel = (lane >> 4) << 3;
    const int gr = lane >> 2;
    const int gc = lane & 3;
    const int qw = wid * 16;

    MBARRIER_WAIT_PARITY(QBAR, 0);

    uint32_t aq[4][4];
    {
        const int qrow = qw + rsel;
        const uint32_t qsw = (uint32_t)((qrow & 7) << 4);
#pragma unroll
        for (int kc = 0; kc < 4; kc++) {
            const uint32_t kb = (uint32_t)((kc * 16 + ksel) * 2);
            ldsm_x4(aq[kc], SQ + qrow * 128 + (kb ^ qsw));
        }
    }

    for (int i = 0; i < T; i++) {
        const int st = i & 1;
        MBARRIER_WAIT_PARITY(FULLB + 8 * st, (i >> 1) & 1);
        const uint32_t Kb = SKV + st * 16384;
        const uint32_t Vb = Kb + 8192;

        float c[8][4];
#pragma unroll
        for (int nt = 0; nt < 8; nt++)
#pragma unroll
            for (int r = 0; r < 4; r++) c[nt][r] = 0.0f;

#pragma unroll
        for (int kc = 0; kc < 4; kc++) {
            const uint32_t kb = (uint32_t)((kc * 16 + ksel) * 2);
#pragma unroll
            for (int ntp = 0; ntp < 4; ntp++) {
                const int krow = ntp * 16 + rsel;
                const uint32_t koff = kb ^ ((krow & 7) << 4);
                uint32_t kh4[4];
                ldsm_x4(kh4, Kb + krow * 128 + koff);
                mma_f16(c[ntp * 2 + 0], aq[kc], kh4[0], kh4[2]);
                mma_f16(c[ntp * 2 + 1], aq[kc], kh4[1], kh4[3]);
            }
        }

        const int kv0 = i * 64;
        const int row0 = q0 + qw + gr;
        if (kv0 + 63 > q0 + qw) {
#pragma unroll
            for (int nt = 0; nt < 8; nt++) {
                const int col = kv0 + nt * 8 + gc * 2;
                if (col     > row0)     c[nt][0] = -1e30f;
                if (col + 1 > row0)     c[nt][1] = -1e30f;
                if (col     > row0 + 8) c[nt][2] = -1e30f;
                if (col + 1 > row0 + 8) c[nt][3] = -1e30f;
            }
        }

#pragma unroll
        for (int h2 = 0; h2 < 2; h2++) {
            float rm = -1e30f;
#pragma unroll
            for (int nt = 0; nt < 8; nt++)
                rm = fmaxf(rm, fmaxf(c[nt][h2 * 2], c[nt][h2 * 2 + 1]));
            rm = fmaxf(rm, __shfl_xor_sync(0xffffffffu, rm, 1));
            rm = fmaxf(rm, __shfl_xor_sync(0xffffffffu, rm, 2));
            const float mn = fmaxf(mi[h2], rm);
            const float corr = __expf(mi[h2] - mn);
            mi[h2] = mn;
            float rs = 0.0f;
#pragma unroll
            for (int nt = 0; nt < 8; nt++) {
                float p0 = __expf(c[nt][h2 * 2] - mn);
                float p1 = __expf(c[nt][h2 * 2 + 1] - mn);
                c[nt][h2 * 2] = p0; c[nt][h2 * 2 + 1] = p1;
                rs += p0 + p1;
            }
            rs += __shfl_xor_sync(0xffffffffu, rs, 1);
            rs += __shfl_xor_sync(0xffffffffu, rs, 2);
            li[h2] = li[h2] * corr + rs;
#pragma unroll
            for (int nt = 0; nt < 8; nt++) {
                o[nt][h2 * 2] *= corr; o[nt][h2 * 2 + 1] *= corr;
            }
        }

#pragma unroll
        for (int kc = 0; kc < 4; kc++) {
            uint32_t ph[4];
            ph[0] = pack_f16(c[2 * kc][0], c[2 * kc][1]);
            ph[1] = pack_f16(c[2 * kc][2], c[2 * kc][3]);
            ph[2] = pack_f16(c[2 * kc + 1][0], c[2 * kc + 1][1]);
            ph[3] = pack_f16(c[2 * kc + 1][2], c[2 * kc + 1][3]);

            const int krow = kc * 16 + rsel;
            const uint32_t swz = (uint32_t)((krow & 7) << 4);
#pragma unroll
            for (int ntd = 0; ntd < 4; ntd++) {
                const uint32_t cb = (uint32_t)((ntd * 16 + ksel) * 2);
                uint32_t vh4[4];
                ldsm_x4_t(vh4, Vb + krow * 128 + (cb ^ swz));
                mma_f16(o[ntd * 2 + 0], ph, vh4[0], vh4[1]);
                mma_f16(o[ntd * 2 + 1], ph, vh4[2], vh4[3]);
            }
        }

        __syncthreads();
        if (tid == 0 && i + ATT_STAGES < T) {
            const int j = i + ATT_STAGES;
            const uint32_t full = FULLB + 8 * st;
            MBARRIER_EXPECT_TX(full, 16384);
            const size_t kv = headoff + (size_t)j * 4096;
            bulk_g2s(SKV + st * 16384,        Kh + kv, 8192, full);
            bulk_g2s(SKV + st * 16384 + 8192, Vh + kv, 8192, full);
        }
    }

    const float inv0 = 1.0f / li[0];
    const float inv1 = 1.0f / li[1];
    const int mrow0 = bb * SEQ + q0 + qw + gr;
#pragma unroll
    for (int nt = 0; nt < 8; nt++) {
        const int dcol = nt * 8 + gc * 2;
#pragma unroll
        for (int h2 = 0; h2 < 2; h2++) {
            const int m = mrow0 + h2 * 8;
            const float vx = o[nt][h2 * 2] * (h2 ? inv1 : inv0);
            const float vy = o[nt][h2 * 2 + 1] * (h2 ? inv1 : inv0);
            const int rb = m >> 7;
            const int rr = m & 127;
            size_t blkbytes = ((size_t)(hh * MBTOT + rb)) * 16384;
            uint32_t off = (uint32_t)(rr * 128 + dcol * 2);
            off ^= (off >> 3) & 0x70;
            *(uint32_t*)((char*)g_ctx2hi + blkbytes + off) = pack_f16(vx, vy);
        }
    }
}

// ---------------------------------------------------------------------------
// LayerNorm; optionally also writes fp16 chunks.
// ---------------------------------------------------------------------------
__global__ void __launch_bounds__(256) ln_kernel(
    const float* __restrict__ in, const float* __restrict__ sc,
    const float* __restrict__ bi, float* __restrict__ out,
    __half* __restrict__ hi)
{
    __shared__ float red0[8], red1[8];
    __shared__ float s_mu, s_inv;
    const int row = blockIdx.x;
    const int tid = threadIdx.x;

    float4 x = ((const float4*)(in + (size_t)row * DMODEL))[tid];
    float sum = x.x + x.y + x.z + x.w;
    float sq  = x.x * x.x + x.y * x.y + x.z * x.z + x.w * x.w;
#pragma unroll
    for (int o = 16; o; o >>= 1) {
        sum += __shfl_xor_sync(0xffffffffu, sum, o);
        sq  += __shfl_xor_sync(0xffffffffu, sq, o);
    }
    if ((tid & 31) == 0) { red0[tid >> 5] = sum; red1[tid >> 5] = sq; }
    __syncthreads();
    if (tid < 32) {
        float s = (tid < 8) ? red0[tid] : 0.0f;
        float q = (tid < 8) ? red1[tid] : 0.0f;
#pragma unroll
        for (int o = 4; o; o >>= 1) {
            s += __shfl_xor_sync(0xffffffffu, s, o);
            q += __shfl_xor_sync(0xffffffffu, q, o);
        }
        if (tid == 0) {
            float mu = s * (1.0f / DMODEL);
            float var = q * (1.0f / DMODEL) - mu * mu;
            s_mu = mu;
            s_inv = rsqrtf(var + 1e-5f);
        }
    }
    __syncthreads();
    const float mu = s_mu, inv = s_inv;
    float4 g = ((const float4*)sc)[tid];
    float4 b = ((const float4*)bi)[tid];
    float4 o;
    o.x = (x.x - mu) * inv * g.x + b.x;
    o.y = (x.y - mu) * inv * g.y + b.y;
    o.z = (x.z - mu) * inv * g.z + b.z;
    o.w = (x.w - mu) * inv * g.w + b.w;
    ((float4*)(out + (size_t)row * DMODEL))[tid] = o;

    if (hi) {
        const int col = tid * 4;
        const int kc = col >> 6;
        const int c = col & 63;
        const int rb = row >> 7;
        const int rr = row & 127;
        size_t blkbytes = ((size_t)(kc * MBTOT + rb)) * 16384;
        uint32_t off = (uint32_t)(rr * 128 + c * 2);
        off ^= (off >> 3) & 0x70;
        uint2 hu;
        hu.x = pack_f16(o.x, o.y);
        hu.y = pack_f16(o.z, o.w);
        *reinterpret_cast<uint2*>((char*)hi + blkbytes + off) = hu;
    }
}

// ---------------------------------------------------------------------------
extern "C" void kernel_launch(void* const* d_in, const int* in_sizes, int n_in,
                              void* d_out, int out_size)
{
    (void)in_sizes; (void)n_in; (void)out_size;
    const float* x    = (const float*)d_in[0];
    const float* wq   = (const float*)d_in[2];
    const float* bq   = (const float*)d_in[3];
    const float* wk   = (const float*)d_in[4];
    const float* bk   = (const float*)d_in[5];
    const float* wv   = (const float*)d_in[6];
    const float* bv   = (const float*)d_in[7];
    const float* wo   = (const float*)d_in[8];
    const float* bo   = (const float*)d_in[9];
    const float* w1   = (const float*)d_in[10];
    const float* b1   = (const float*)d_in[11];
    const float* w2   = (const float*)d_in[12];
    const float* b2   = (const float*)d_in[13];
    const float* ln1s = (const float*)d_in[14];
    const float* ln1b = (const float*)d_in[15];
    const float* ln2s = (const float*)d_in[16];
    const float* ln2b = (const float*)d_in[17];
    float* out = (float*)d_out;

    float *res1, *h, *res2, *bqkv;
    cudaGetSymbolAddress((void**)&res1, g_res1);
    cudaGetSymbolAddress((void**)&h,    g_h);
    cudaGetSymbolAddress((void**)&res2, g_res2);
    cudaGetSymbolAddress((void**)&bqkv, g_bqkv);

    __half *x2h, *c2h, *h2h, *f2h;
    __half *wqkvh, *woh, *w1h, *w2h;
    __half *qh, *kh, *vh;
    cudaGetSymbolAddress((void**)&x2h, g_x2hi);
    cudaGetSymbolAddress((void**)&c2h, g_ctx2hi);
    cudaGetSymbolAddress((void**)&h2h, g_h2hi);
    cudaGetSymbolAddress((void**)&f2h, g_ff2hi);
    cudaGetSymbolAddress((void**)&wqkvh, g_wqkvhi);
    cudaGetSymbolAddress((void**)&woh, g_wohi);
    cudaGetSymbolAddress((void**)&w1h, g_w1hi);
    cudaGetSymbolAddress((void**)&w2h, g_w2hi);
    cudaGetSymbolAddress((void**)&qh, g_Qh);
    cudaGetSymbolAddress((void**)&kh, g_Kh);
    cudaGetSymbolAddress((void**)&vh, g_Vh);

    cudaFuncSetAttribute(tc_gemm<0>, cudaFuncAttributeMaxDynamicSharedMemorySize, GEMM_SMEM_BYTES);
    cudaFuncSetAttribute(tc_gemm<1>, cudaFuncAttributeMaxDynamicSharedMemorySize, GEMM_SMEM_BYTES);
    cudaFuncSetAttribute(tc_gemm<2>, cudaFuncAttributeMaxDynamicSharedMemorySize, GEMM_SMEM_BYTES);
    cudaFuncSetAttribute(attn_mma_kernel, cudaFuncAttributeMaxDynamicSharedMemorySize, ATT_SMEM);

    const dim3 blk256(256);
    const dim3 blkg(GEMM_THREADS);

    // --- all conversions + bias concat in one launch (vectorized) ---
    convert_all_kernel<<<5123, blk256>>>(x, wq, wk, wv, wo, w1, w2, bq, bk, bv);

    // --- QKV fused GEMM (N=3072) -> fp16 per-head tiles ---
    tc_gemm<0><<<dim3(24, MBTOT), blkg, GEMM_SMEM_BYTES>>>(
        x2h, wqkvh, DMODEL / 64, MBTOT, 24, bqkv, nullptr, nullptr, 3072);

    // --- HMMA flash attention -> ctx fp16 chunks ---
    attn_mma_kernel<<<dim3(SEQ / 64, NHEAD, BATCH), 128, ATT_SMEM>>>(qh, kh, vh);

    // --- O projection + residual(x) -> res1; LN1 -> h (fp32 + fp16 chunks) ---
    tc_gemm<1><<<dim3(8, MBTOT), blkg, GEMM_SMEM_BYTES>>>(
        c2h, woh, DMODEL / 64, MBTOT, 8, bo, x, res1, DMODEL);
    ln_kernel<<<MROWS, blk256>>>(res1, ln1s, ln1b, h, h2h);

    // --- FFN1 + GELU -> ff fp16 chunks directly ---
    tc_gemm<2><<<dim3(32, MBTOT), blkg, GEMM_SMEM_BYTES>>>(
        h2h, w1h, DMODEL / 64, MBTOT, 32, b1, nullptr, nullptr, DFF);

    // --- FFN2 + residual(h) -> res2; LN2 -> out ---
    tc_gemm<1><<<dim3(8, MBTOT), blkg, GEMM_SMEM_BYTES>>>(
        f2h, w2h, DFF / 64, MBTOT, 8, b2, h, res2, DMODEL);
    ln_kernel<<<MROWS, blk256>>>(res2, ln2s, ln2b, out, nullptr);
}